// round 1
// baseline (speedup 1.0000x reference)
#include <cuda_runtime.h>

#define BS_   2
#define SEQ   2048
#define HID   1024
#define HEADS 16
#define HD    64
#define NTOK  (BS_*SEQ)   // 4096

// Scratch (allocation-free rule: __device__ globals)
__device__ float g_Q[NTOK*HID];
__device__ float g_K[NTOK*HID];
__device__ float g_V[NTOK*HID];
__device__ float g_A[NTOK*HID];

// ---------------------------------------------------------------------------
// SGEMM: C[M,N] = A[M,K] * B[N,K]^T + bias   (both operands K-contiguous,
// matching torch Linear y = x @ W.T + b with row-major W[out,in])
// 128x128 tile, BK=16, 256 threads, 8x8 per-thread (2x2 blocks of 4x4).
// ---------------------------------------------------------------------------
#define BM  128
#define BN  128
#define BKK 16

__global__ void __launch_bounds__(256) sgemm_bias_kernel(
    const float* __restrict__ A, const float* __restrict__ B,
    const float* __restrict__ bias, float* __restrict__ C,
    int M, int N, int K)
{
    __shared__ float As[BKK][BM];
    __shared__ float Bs[BKK][BN];
    const int tid  = threadIdx.x;
    const int brow = blockIdx.y * BM;
    const int bcol = blockIdx.x * BN;
    const int tr   = (tid >> 4) * 4;   // 0..60
    const int tc   = (tid & 15) * 4;   // 0..60
    const int lr   = tid >> 2;         // 0..63
    const int lc4  = tid & 3;          // float4 slot 0..3

    float acc[8][8];
    #pragma unroll
    for (int i = 0; i < 8; i++)
        #pragma unroll
        for (int j = 0; j < 8; j++) acc[i][j] = 0.f;

    for (int k0 = 0; k0 < K; k0 += BKK) {
        #pragma unroll
        for (int i = 0; i < 2; i++) {
            int r = lr + i * 64;
            float4 va = *(const float4*)(A + (size_t)(brow + r) * K + k0 + lc4 * 4);
            As[lc4*4+0][r] = va.x; As[lc4*4+1][r] = va.y;
            As[lc4*4+2][r] = va.z; As[lc4*4+3][r] = va.w;
            float4 vb = *(const float4*)(B + (size_t)(bcol + r) * K + k0 + lc4 * 4);
            Bs[lc4*4+0][r] = vb.x; Bs[lc4*4+1][r] = vb.y;
            Bs[lc4*4+2][r] = vb.z; Bs[lc4*4+3][r] = vb.w;
        }
        __syncthreads();
        #pragma unroll
        for (int kk = 0; kk < BKK; kk++) {
            float a[8], b[8];
            #pragma unroll
            for (int i = 0; i < 4; i++) {
                a[i]   = As[kk][tr + i];
                a[i+4] = As[kk][tr + 64 + i];
            }
            #pragma unroll
            for (int j = 0; j < 4; j++) {
                b[j]   = Bs[kk][tc + j];
                b[j+4] = Bs[kk][tc + 64 + j];
            }
            #pragma unroll
            for (int i = 0; i < 8; i++)
                #pragma unroll
                for (int j = 0; j < 8; j++)
                    acc[i][j] = fmaf(a[i], b[j], acc[i][j]);
        }
        __syncthreads();
    }

    #pragma unroll
    for (int i = 0; i < 8; i++) {
        int row = brow + tr + (i < 4 ? i : 64 + (i - 4));
        #pragma unroll
        for (int j = 0; j < 8; j++) {
            int col = bcol + tc + (j < 4 ? j : 64 + (j - 4));
            C[(size_t)row * N + col] = acc[i][j] + bias[col];
        }
    }
}

// ---------------------------------------------------------------------------
// Flash-style attention, fp32, 64x64 tiles.
// BLOCK(=64)-level causal mask == tile skipping, no per-element mask needed.
// grid = (SEQ/64, HEADS, BS). 256 threads = 8 warps; warp w owns q-rows
// w*8 .. w*8+7. Lane holds head-dims (lane, lane+32) of the output accum.
// ---------------------------------------------------------------------------
__global__ void __launch_bounds__(256) attn_kernel(
    const float* __restrict__ Q, const float* __restrict__ K,
    const float* __restrict__ V, float* __restrict__ O)
{
    extern __shared__ float sm[];
    float* Qs = sm;             // [64][64]
    float* Ks = Qs + 64 * 64;   // [64][65]  (pad: lane-indexed row reads)
    float* Vs = Ks + 64 * 65;   // [64][64]
    float* Ps = Vs + 64 * 64;   // [64][64]

    const int qt = blockIdx.x, h = blockIdx.y, b = blockIdx.z;
    const int tid = threadIdx.x, w = tid >> 5, lane = tid & 31;
    const float scale = 0.125f;  // 1/sqrt(64)

    const float* qbase = Q + ((size_t)(b * SEQ + qt * 64)) * HID + h * HD;
    for (int i = tid; i < 64 * 16; i += 256) {
        int r = i >> 4, c4 = i & 15;
        *(float4*)(Qs + r * 64 + c4 * 4) =
            *(const float4*)(qbase + (size_t)r * HID + c4 * 4);
    }

    float m[8], l[8], o0[8], o1[8];
    #pragma unroll
    for (int r = 0; r < 8; r++) { m[r] = -1e30f; l[r] = 0.f; o0[r] = 0.f; o1[r] = 0.f; }

    for (int kt = 0; kt <= qt; kt++) {
        __syncthreads();
        const float* kbase = K + ((size_t)(b * SEQ + kt * 64)) * HID + h * HD;
        const float* vbase = V + ((size_t)(b * SEQ + kt * 64)) * HID + h * HD;
        for (int i = tid; i < 64 * 16; i += 256) {
            int r = i >> 4, c4 = i & 15;
            float4 kv = *(const float4*)(kbase + (size_t)r * HID + c4 * 4);
            Ks[r*65 + c4*4+0] = kv.x; Ks[r*65 + c4*4+1] = kv.y;
            Ks[r*65 + c4*4+2] = kv.z; Ks[r*65 + c4*4+3] = kv.w;
            *(float4*)(Vs + r * 64 + c4 * 4) =
                *(const float4*)(vbase + (size_t)r * HID + c4 * 4);
        }
        __syncthreads();

        #pragma unroll
        for (int rr = 0; rr < 8; rr += 4) {
            // S = Q·K^T for 4 rows; lane covers cols (lane, lane+32)
            float s0[4], s1[4];
            #pragma unroll
            for (int r = 0; r < 4; r++) { s0[r] = 0.f; s1[r] = 0.f; }
            const float* k0p = Ks + lane * 65;
            const float* k1p = k0p + 32 * 65;
            #pragma unroll
            for (int k = 0; k < 64; k++) {
                float kv0 = k0p[k], kv1 = k1p[k];
                #pragma unroll
                for (int r = 0; r < 4; r++) {
                    float qv = Qs[(w * 8 + rr + r) * 64 + k];
                    s0[r] = fmaf(qv, kv0, s0[r]);
                    s1[r] = fmaf(qv, kv1, s1[r]);
                }
            }
            // online softmax per row
            #pragma unroll
            for (int r = 0; r < 4; r++) {
                const int ri = rr + r;
                const int qr = w * 8 + ri;
                float a = s0[r] * scale, c = s1[r] * scale;
                float mx = fmaxf(a, c);
                #pragma unroll
                for (int off = 16; off; off >>= 1)
                    mx = fmaxf(mx, __shfl_xor_sync(0xffffffffu, mx, off));
                float mnew = fmaxf(m[ri], mx);
                float corr = __expf(m[ri] - mnew);
                float p0 = __expf(a - mnew);
                float p1 = __expf(c - mnew);
                float ps = p0 + p1;
                #pragma unroll
                for (int off = 16; off; off >>= 1)
                    ps += __shfl_xor_sync(0xffffffffu, ps, off);
                m[ri] = mnew;
                l[ri] = l[ri] * corr + ps;
                o0[ri] *= corr; o1[ri] *= corr;
                Ps[qr * 64 + lane]      = p0;
                Ps[qr * 64 + lane + 32] = p1;
            }
            __syncwarp();
            // O += P·V for the same 4 rows
            #pragma unroll
            for (int c = 0; c < 64; c++) {
                float v0 = Vs[c * 64 + lane];
                float v1 = Vs[c * 64 + lane + 32];
                #pragma unroll
                for (int r = 0; r < 4; r++) {
                    float p = Ps[(w * 8 + rr + r) * 64 + c];
                    o0[rr + r] = fmaf(p, v0, o0[rr + r]);
                    o1[rr + r] = fmaf(p, v1, o1[rr + r]);
                }
            }
            __syncwarp();
        }
    }

    float* obase = O + ((size_t)(b * SEQ + qt * 64)) * HID + h * HD;
    #pragma unroll
    for (int r = 0; r < 8; r++) {
        int qr = w * 8 + r;
        float inv = 1.f / l[r];
        obase[(size_t)qr * HID + lane]      = o0[r] * inv;
        obase[(size_t)qr * HID + lane + 32] = o1[r] * inv;
    }
}

// ---------------------------------------------------------------------------
extern "C" void kernel_launch(void* const* d_in, const int* in_sizes, int n_in,
                              void* d_out, int out_size) {
    const float* X  = (const float*)d_in[0];
    const float* Wq = (const float*)d_in[1];
    const float* bq = (const float*)d_in[2];
    const float* Wk = (const float*)d_in[3];
    const float* bk = (const float*)d_in[4];
    const float* Wv = (const float*)d_in[5];
    const float* bv = (const float*)d_in[6];
    const float* Wo = (const float*)d_in[7];
    const float* bo = (const float*)d_in[8];
    float* out = (float*)d_out;

    float *Qp, *Kp, *Vp, *Ap;
    cudaGetSymbolAddress((void**)&Qp, g_Q);
    cudaGetSymbolAddress((void**)&Kp, g_K);
    cudaGetSymbolAddress((void**)&Vp, g_V);
    cudaGetSymbolAddress((void**)&Ap, g_A);

    dim3 gblk(HID / BN, NTOK / BM);  // (8, 32)
    sgemm_bias_kernel<<<gblk, 256>>>(X, Wq, bq, Qp, NTOK, HID, HID);
    sgemm_bias_kernel<<<gblk, 256>>>(X, Wk, bk, Kp, NTOK, HID, HID);
    sgemm_bias_kernel<<<gblk, 256>>>(X, Wv, bv, Vp, NTOK, HID, HID);

    const int smem = (64*64 + 64*65 + 64*64 + 64*64) * (int)sizeof(float);
    cudaFuncSetAttribute(attn_kernel,
                         cudaFuncAttributeMaxDynamicSharedMemorySize, smem);
    attn_kernel<<<dim3(SEQ / 64, HEADS, BS_), 256, smem>>>(Qp, Kp, Vp, Ap);

    sgemm_bias_kernel<<<gblk, 256>>>(Ap, Wo, bo, out, NTOK, HID, HID);
}

// round 13
// speedup vs baseline: 3.1774x; 3.1774x over previous
#include <cuda_runtime.h>
#include <cstdint>

#define BS_   2
#define SEQ   2048
#define HID   1024
#define HEADS 16
#define HD    64
#define NTOK  (BS_*SEQ)   // 4096

// Scratch (allocation-free rule: __device__ globals)
__device__ float g_Q[NTOK*HID];
__device__ float g_K[NTOK*HID];
__device__ float g_V[NTOK*HID];
__device__ float g_A[NTOK*HID];

// ===========================================================================
// helpers
// ===========================================================================
__device__ __forceinline__ uint32_t smem_u32(const void* p) {
    uint32_t a;
    asm("{ .reg .u64 t; cvta.to.shared.u64 t, %1; cvt.u32.u64 %0, t; }"
        : "=r"(a) : "l"(p));
    return a;
}
__device__ __forceinline__ void cp_async16(uint32_t dst, const void* src) {
    asm volatile("cp.async.cg.shared.global [%0], [%1], 16;"
                 :: "r"(dst), "l"(src) : "memory");
}
#define CP_COMMIT() asm volatile("cp.async.commit_group;" ::: "memory")
#define CP_WAIT(n)  asm volatile("cp.async.wait_group %0;" :: "n"(n) : "memory")

// round-to-nearest fp32 -> tf32 (kills RZ truncation bias; keeps rel_err ~1e-4)
__device__ __forceinline__ uint32_t f2tf32(float f) {
    uint32_t r;
    asm("cvt.rna.tf32.f32 %0, %1;" : "=r"(r) : "f"(f));
    return r;
}

// m16n8k8 tf32 MMA (A row-major, B col-major), fp32 accum
// A frag: a0=(gid,tg) a1=(gid+8,tg) a2=(gid,tg+4) a3=(gid+8,tg+4)
// B frag: b0=(k=tg,n=gid) b1=(k=tg+4,n=gid)
// C frag: c0=(gid,2tg) c1=(gid,2tg+1) c2=(gid+8,2tg) c3=(gid+8,2tg+1)
__device__ __forceinline__ void mma_tf32(float* c, const uint32_t* a,
                                         const uint32_t* b) {
    asm volatile(
        "mma.sync.aligned.m16n8k8.row.col.f32.tf32.tf32.f32 "
        "{%0,%1,%2,%3}, {%4,%5,%6,%7}, {%8,%9}, {%0,%1,%2,%3};"
        : "+f"(c[0]), "+f"(c[1]), "+f"(c[2]), "+f"(c[3])
        : "r"(a[0]), "r"(a[1]), "r"(a[2]), "r"(a[3]), "r"(b[0]), "r"(b[1]));
}

// ===========================================================================
// TF32 mma.sync GEMM: C[M,N] = A[M,K] * B[N,K]^T + bias
// ===========================================================================
#define BM  128
#define BN  128
#define BK  32
#define LDP (BK + 4)
#define TILE_F (BM * LDP)
#define GM_SMEM (4 * TILE_F * (int)sizeof(float))

__global__ void __launch_bounds__(256) gemm_tf32_kernel(
    const float* __restrict__ A, const float* __restrict__ B,
    const float* __restrict__ bias, float* __restrict__ C)
{
    constexpr int N = HID, K = HID;
    constexpr int NT = K / BK;
    extern __shared__ float sm[];
    float* As = sm;
    float* Bs = sm + 2 * TILE_F;

    const int tid  = threadIdx.x;
    const int wid  = tid >> 5, lane = tid & 31;
    const int wm   = wid >> 2, wn = wid & 3;
    const int gid  = lane >> 2, tg = lane & 3;
    const int brow = blockIdx.y * BM;
    const int bcol = blockIdx.x * BN;

    float acc[4][4][4];
    #pragma unroll
    for (int i = 0; i < 4; i++)
        #pragma unroll
        for (int j = 0; j < 4; j++)
            #pragma unroll
            for (int e = 0; e < 4; e++) acc[i][j][e] = 0.f;

    const uint32_t sA0 = smem_u32(As);
    const uint32_t sB0 = smem_u32(Bs);

    auto load_tile = [&](int buf, int k0) {
        const uint32_t dA = sA0 + buf * TILE_F * 4;
        const uint32_t dB = sB0 + buf * TILE_F * 4;
        #pragma unroll
        for (int i = 0; i < 4; i++) {
            int idx = tid + i * 256;
            int row = idx >> 3, c4 = idx & 7;
            cp_async16(dA + (row * LDP + c4 * 4) * 4,
                       A + (size_t)(brow + row) * K + k0 + c4 * 4);
            cp_async16(dB + (row * LDP + c4 * 4) * 4,
                       B + (size_t)(bcol + row) * K + k0 + c4 * 4);
        }
        CP_COMMIT();
    };

    load_tile(0, 0);

    for (int t = 0; t < NT; t++) {
        const int cur = t & 1;
        if (t + 1 < NT) { load_tile(1 - cur, (t + 1) * BK); CP_WAIT(1); }
        else            { CP_WAIT(0); }
        __syncthreads();

        const float* wA = As + cur * TILE_F + (wm * 64) * LDP;
        const float* wB = Bs + cur * TILE_F + (wn * 32) * LDP;

        #pragma unroll
        for (int ks = 0; ks < 4; ks++) {
            const int kb = ks * 8;
            uint32_t a[4][4], b[4][2];
            #pragma unroll
            for (int mt = 0; mt < 4; mt++) {
                const float* p = wA + (mt * 16 + gid) * LDP + kb + tg;
                a[mt][0] = f2tf32(p[0]);
                a[mt][1] = f2tf32(p[8 * LDP]);
                a[mt][2] = f2tf32(p[4]);
                a[mt][3] = f2tf32(p[8 * LDP + 4]);
            }
            #pragma unroll
            for (int nt = 0; nt < 4; nt++) {
                const float* p = wB + (nt * 8 + gid) * LDP + kb + tg;
                b[nt][0] = f2tf32(p[0]);
                b[nt][1] = f2tf32(p[4]);
            }
            #pragma unroll
            for (int mt = 0; mt < 4; mt++)
                #pragma unroll
                for (int nt = 0; nt < 4; nt++)
                    mma_tf32(acc[mt][nt], a[mt], b[nt]);
        }
        __syncthreads();
    }

    const int rbase = brow + wm * 64;
    const int cbase = bcol + wn * 32;
    #pragma unroll
    for (int mt = 0; mt < 4; mt++) {
        #pragma unroll
        for (int nt = 0; nt < 4; nt++) {
            const int r0 = rbase + mt * 16 + gid;
            const int c0 = cbase + nt * 8 + tg * 2;
            float2 bv = *(const float2*)(bias + c0);
            float2 v0 = { acc[mt][nt][0] + bv.x, acc[mt][nt][1] + bv.y };
            float2 v1 = { acc[mt][nt][2] + bv.x, acc[mt][nt][3] + bv.y };
            *(float2*)(C + (size_t)r0 * N + c0)       = v0;
            *(float2*)(C + (size_t)(r0 + 8) * N + c0) = v1;
        }
    }
}

// ===========================================================================
// Flash attention on tf32 mma.sync. 64x64 tiles, 4 warps (128 thr).
// ===========================================================================
#define ALD 68
#define AT_SMEM (4 * 64 * ALD * (int)sizeof(float))   // 69632B

__global__ void __launch_bounds__(128) attn_kernel(
    const float* __restrict__ Q, const float* __restrict__ K,
    const float* __restrict__ V, float* __restrict__ O)
{
    extern __shared__ float smf[];
    float* Qs = smf;              // [64][ALD]
    float* Ks = Qs + 64 * ALD;
    float* Vs = Ks + 64 * ALD;
    float* Ps = Vs + 64 * ALD;

    const int qt = blockIdx.x, h = blockIdx.y, b = blockIdx.z;
    const int tid = threadIdx.x, wid = tid >> 5, lane = tid & 31;
    const int gid = lane >> 2, tg = lane & 3;
    const int mbase = wid * 16;

    // Load Q tile pre-scaled by 1/sqrt(64)
    const float* qbase = Q + ((size_t)(b * SEQ + qt * 64)) * HID + h * HD;
    for (int i = tid; i < 64 * 16; i += 128) {
        int r = i >> 4, c4 = i & 15;
        float4 v = *(const float4*)(qbase + (size_t)r * HID + c4 * 4);
        v.x *= 0.125f; v.y *= 0.125f; v.z *= 0.125f; v.w *= 0.125f;
        *(float4*)(Qs + r * ALD + c4 * 4) = v;
    }

    float m0 = -1e30f, m1 = -1e30f, l0 = 0.f, l1 = 0.f;
    float o[8][4];
    #pragma unroll
    for (int i = 0; i < 8; i++)
        #pragma unroll
        for (int e = 0; e < 4; e++) o[i][e] = 0.f;

    for (int kt = 0; kt <= qt; kt++) {
        __syncthreads();
        const float* kbase = K + ((size_t)(b * SEQ + kt * 64)) * HID + h * HD;
        const float* vbase = V + ((size_t)(b * SEQ + kt * 64)) * HID + h * HD;
        for (int i = tid; i < 64 * 16; i += 128) {
            int r = i >> 4, c4 = i & 15;
            *(float4*)(Ks + r * ALD + c4 * 4) =
                *(const float4*)(kbase + (size_t)r * HID + c4 * 4);
            *(float4*)(Vs + r * ALD + c4 * 4) =
                *(const float4*)(vbase + (size_t)r * HID + c4 * 4);
        }
        __syncthreads();

        // ---- S = Qs * Ks^T  (per-warp m16 x n64, k=64) ----
        float s[8][4];
        #pragma unroll
        for (int i = 0; i < 8; i++)
            #pragma unroll
            for (int e = 0; e < 4; e++) s[i][e] = 0.f;

        #pragma unroll
        for (int kf = 0; kf < 8; kf++) {
            const int kb = kf * 8;
            uint32_t a[4];
            const float* pa = Qs + (mbase + gid) * ALD + kb + tg;
            a[0] = f2tf32(pa[0]);
            a[1] = f2tf32(pa[8 * ALD]);
            a[2] = f2tf32(pa[4]);
            a[3] = f2tf32(pa[8 * ALD + 4]);
            #pragma unroll
            for (int nt = 0; nt < 8; nt++) {
                uint32_t bf[2];
                const float* pb = Ks + (nt * 8 + gid) * ALD + kb + tg;
                bf[0] = f2tf32(pb[0]);
                bf[1] = f2tf32(pb[4]);
                mma_tf32(s[nt], a, bf);
            }
        }

        // ---- online softmax on fragment rows gid / gid+8 ----
        float mx0 = -1e30f, mx1 = -1e30f;
        #pragma unroll
        for (int nt = 0; nt < 8; nt++) {
            mx0 = fmaxf(mx0, fmaxf(s[nt][0], s[nt][1]));
            mx1 = fmaxf(mx1, fmaxf(s[nt][2], s[nt][3]));
        }
        mx0 = fmaxf(mx0, __shfl_xor_sync(0xffffffffu, mx0, 1));
        mx0 = fmaxf(mx0, __shfl_xor_sync(0xffffffffu, mx0, 2));
        mx1 = fmaxf(mx1, __shfl_xor_sync(0xffffffffu, mx1, 1));
        mx1 = fmaxf(mx1, __shfl_xor_sync(0xffffffffu, mx1, 2));

        const float mn0 = fmaxf(m0, mx0), mn1 = fmaxf(m1, mx1);
        const float cr0 = __expf(m0 - mn0), cr1 = __expf(m1 - mn1);
        float sum0 = 0.f, sum1 = 0.f;
        float* pr0 = Ps + (mbase + gid) * ALD + 2 * tg;
        float* pr1 = pr0 + 8 * ALD;
        #pragma unroll
        for (int nt = 0; nt < 8; nt++) {
            float p00 = __expf(s[nt][0] - mn0);
            float p01 = __expf(s[nt][1] - mn0);
            float p10 = __expf(s[nt][2] - mn1);
            float p11 = __expf(s[nt][3] - mn1);
            sum0 += p00 + p01;
            sum1 += p10 + p11;
            *(float2*)(pr0 + nt * 8) = make_float2(p00, p01);
            *(float2*)(pr1 + nt * 8) = make_float2(p10, p11);
        }
        sum0 += __shfl_xor_sync(0xffffffffu, sum0, 1);
        sum0 += __shfl_xor_sync(0xffffffffu, sum0, 2);
        sum1 += __shfl_xor_sync(0xffffffffu, sum1, 1);
        sum1 += __shfl_xor_sync(0xffffffffu, sum1, 2);

        m0 = mn0; m1 = mn1;
        l0 = l0 * cr0 + sum0;
        l1 = l1 * cr1 + sum1;
        #pragma unroll
        for (int nt = 0; nt < 8; nt++) {
            o[nt][0] *= cr0; o[nt][1] *= cr0;
            o[nt][2] *= cr1; o[nt][3] *= cr1;
        }
        __syncwarp();

        // ---- O += P * V ----
        #pragma unroll
        for (int kf = 0; kf < 8; kf++) {
            const int kb = kf * 8;
            uint32_t a[4];
            const float* pa = Ps + (mbase + gid) * ALD + kb + tg;
            a[0] = f2tf32(pa[0]);
            a[1] = f2tf32(pa[8 * ALD]);
            a[2] = f2tf32(pa[4]);
            a[3] = f2tf32(pa[8 * ALD + 4]);
            #pragma unroll
            for (int nt = 0; nt < 8; nt++) {
                uint32_t bf[2];
                const float* pb = Vs + (kb + tg) * ALD + nt * 8 + gid;
                bf[0] = f2tf32(pb[0]);
                bf[1] = f2tf32(pb[4 * ALD]);
                mma_tf32(o[nt], a, bf);
            }
        }
    }

    // ---- epilogue ----
    const float inv0 = 1.f / l0, inv1 = 1.f / l1;
    float* ob = O + ((size_t)(b * SEQ + qt * 64 + mbase)) * HID + h * HD;
    #pragma unroll
    for (int nt = 0; nt < 8; nt++) {
        const int col = nt * 8 + 2 * tg;
        *(float2*)(ob + (size_t)gid * HID + col) =
            make_float2(o[nt][0] * inv0, o[nt][1] * inv0);
        *(float2*)(ob + (size_t)(gid + 8) * HID + col) =
            make_float2(o[nt][2] * inv1, o[nt][3] * inv1);
    }
}

// ---------------------------------------------------------------------------
extern "C" void kernel_launch(void* const* d_in, const int* in_sizes, int n_in,
                              void* d_out, int out_size) {
    const float* X  = (const float*)d_in[0];
    const float* Wq = (const float*)d_in[1];
    const float* bq = (const float*)d_in[2];
    const float* Wk = (const float*)d_in[3];
    const float* bk = (const float*)d_in[4];
    const float* Wv = (const float*)d_in[5];
    const float* bv = (const float*)d_in[6];
    const float* Wo = (const float*)d_in[7];
    const float* bo = (const float*)d_in[8];
    float* out = (float*)d_out;

    float *Qp, *Kp, *Vp, *Ap;
    cudaGetSymbolAddress((void**)&Qp, g_Q);
    cudaGetSymbolAddress((void**)&Kp, g_K);
    cudaGetSymbolAddress((void**)&Vp, g_V);
    cudaGetSymbolAddress((void**)&Ap, g_A);

    cudaFuncSetAttribute(gemm_tf32_kernel,
                         cudaFuncAttributeMaxDynamicSharedMemorySize, GM_SMEM);
    cudaFuncSetAttribute(attn_kernel,
                         cudaFuncAttributeMaxDynamicSharedMemorySize, AT_SMEM);

    dim3 gg(HID / BN, NTOK / BM);  // (8, 32) = 256 CTAs
    gemm_tf32_kernel<<<gg, 256, GM_SMEM>>>(X, Wq, bq, Qp);
    gemm_tf32_kernel<<<gg, 256, GM_SMEM>>>(X, Wk, bk, Kp);
    gemm_tf32_kernel<<<gg, 256, GM_SMEM>>>(X, Wv, bv, Vp);

    attn_kernel<<<dim3(SEQ / 64, HEADS, BS_), 128, AT_SMEM>>>(Qp, Kp, Vp, Ap);

    gemm_tf32_kernel<<<gg, 256, GM_SMEM>>>(Ap, Wo, bo, out);
}